// round 12
// baseline (speedup 1.0000x reference)
#include <cuda_runtime.h>
#include <cstdint>

// Problem: input [B=128, C=2, H=512, W=512] fp32.
// out[:,0] = inclusive cumsum along x (contiguous axis)
// out[:,1] = inclusive cumsum along y (stride-W axis)
//
// One fused kernel, all blocks short-lived and bandwidth-bound:
//  x-role (8192 blocks): one warp per row, float4 warp-scan.
//  y-role (4096 blocks): 512x16 tile staged through smem with a per-segment
//    16-float skew (segment stride 528 ≡ 16 mod 32 banks) so the smem scan
//    phase is bank-conflict-free. Load/store phases use identical
//    float4-coalesced mappings. Plain loads/stores (R11 showed __ldcs/__stcs
//    streaming hints REGRESS DRAM throughput on sm_103a here).
// Interleaved bid%3==0 -> y so both traffic types share every wave.

#define Bn 128
#define Wn 512
#define TCOLS 16                    // tile width (columns)
#define TSEG 32                     // rows per scan segment
#define NSEG 16                     // 512 / 32
#define SEG_STRIDE 528              // floats per segment (512 + 16 skew)
#define TILE_FLOATS (NSEG * SEG_STRIDE)   // 8448 floats = 33 KB
#define Y_BLOCKS 4096               // 128 images * (512/16) col-tiles
#define X_BLOCKS 8192               // 65536 rows / 8 warps
#define GRID_BLOCKS (Y_BLOCKS + X_BLOCKS)

// float4 index of row r, group 0, in the skewed tile
__device__ __forceinline__ unsigned trow4(unsigned r) {
    return (r >> 5) * (SEG_STRIDE / 4) + (r & 31u) * 4u;
}

// ---------------------------------------------------------------------------
// x-role: one warp per row of channel 0.
// ---------------------------------------------------------------------------
__device__ __forceinline__ void do_scan_x(const float* __restrict__ in,
                                          float* __restrict__ out,
                                          unsigned xbid) {
    const unsigned gwarp = xbid * 8u + (threadIdx.x >> 5);   // 0..65535
    const unsigned lane  = threadIdx.x & 31u;

    const unsigned b = gwarp >> 9;
    const unsigned y = gwarp & 511u;

    const size_t base = ((size_t)(b * 2u + 0u) * Wn + y) * Wn;  // channel 0
    const float4* __restrict__ in4  = (const float4*)(in + base);
    float4* __restrict__       out4 = (float4*)(out + base);

    float carry = 0.0f;
#pragma unroll
    for (int it = 0; it < 4; ++it) {
        float4 v = in4[it * 32 + lane];

        float s0 = v.x;
        float s1 = s0 + v.y;
        float s2 = s1 + v.z;
        float s3 = s2 + v.w;

        float incl = s3;
#pragma unroll
        for (int off = 1; off < 32; off <<= 1) {
            float n = __shfl_up_sync(0xffffffffu, incl, off);
            if (lane >= (unsigned)off) incl += n;
        }
        float excl = incl - s3 + carry;

        float4 o;
        o.x = s0 + excl;
        o.y = s1 + excl;
        o.z = s2 + excl;
        o.w = s3 + excl;
        out4[it * 32 + lane] = o;

        carry += __shfl_sync(0xffffffffu, incl, 31);
    }
}

// ---------------------------------------------------------------------------
// y-role: 512x16 tile of channel 1 through skewed smem.
// ---------------------------------------------------------------------------
__device__ __forceinline__ void do_scan_y(const float* __restrict__ in,
                                          float* __restrict__ out,
                                          unsigned ybid,
                                          float* __restrict__ tile,
                                          float* __restrict__ spine,
                                          float* __restrict__ pre) {
    const unsigned tid = threadIdx.x;
    const unsigned b   = ybid >> 5;          // image (32 col-tiles per image)
    const unsigned tc  = ybid & 31u;         // col-tile
    const unsigned col0 = tc * TCOLS;

    const size_t base = ((size_t)(b * 2u + 1u) * Wn) * Wn + col0;  // ch1 row0

    const unsigned quad = tid & 3u;          // float4 within 16-col tile row
    const unsigned r0   = tid >> 2;          // 0..63
    float4* __restrict__ tile4 = (float4*)tile;

    // ---- load: 2048 float4s, 8 per thread, coalesced, independent ----
    {
        const float4* __restrict__ in4 = (const float4*)(in + base);
#pragma unroll
        for (int batch = 0; batch < 8; ++batch) {
            const unsigned row = batch * 64u + r0;
            tile4[trow4(row) + quad] = in4[(size_t)row * 128u + quad];
        }
    }
    __syncthreads();

    // ---- scan: thread (c, s) scans rows [s*32, s*32+32) of column c ----
    // Skewed addressing: addr = s*528 + i*16 + c. Segment stride 528 ≡ 16
    // (mod 32 banks) -> the warp's two half-warps hit disjoint bank halves.
    const unsigned c = tid & 15u;
    const unsigned s = tid >> 4;
    {
        float* __restrict__ p = tile + s * SEG_STRIDE + c;
        float acc = 0.0f;
#pragma unroll
        for (int i = 0; i < TSEG; ++i) {
            acc += p[i * TCOLS];
            p[i * TCOLS] = acc;            // in-place inclusive prefix
        }
        spine[s * TCOLS + c] = acc;        // segment total
    }
    __syncthreads();

    // ---- spine prefix: pre[s][c] = sum of spine[s2][c], s2 < s ----
    {
        float off = 0.0f;
        for (unsigned s2 = 0; s2 < s; ++s2)
            off += spine[s2 * TCOLS + c];
        pre[s * TCOLS + c] = off;
    }
    __syncthreads();

    // ---- store: same float4 mapping as load (fully coalesced) ----
    {
        float4* __restrict__ out4 = (float4*)(out + base);
        const float* __restrict__ prow = pre + quad * 4u;   // 4 col offsets
#pragma unroll
        for (int batch = 0; batch < 8; ++batch) {
            const unsigned row = batch * 64u + r0;
            const unsigned seg = row >> 5;                  // row / TSEG
            float4 v = tile4[trow4(row) + quad];
            v.x += prow[seg * TCOLS + 0];
            v.y += prow[seg * TCOLS + 1];
            v.z += prow[seg * TCOLS + 2];
            v.w += prow[seg * TCOLS + 3];
            out4[(size_t)row * 128u + quad] = v;
        }
    }
}

__global__ void __launch_bounds__(256) fused_scan_kernel(const float* __restrict__ in,
                                                         float* __restrict__ out) {
    __shared__ float tile[TILE_FLOATS];      // 33 KB (skewed)
    __shared__ float spine[NSEG * TCOLS];    // 1 KB
    __shared__ float pre[NSEG * TCOLS];      // 1 KB

    const unsigned bid = blockIdx.x;
    const unsigned q = bid / 3u;
    if (bid == q * 3u) {
        do_scan_y(in, out, q, tile, spine, pre);     // 4096 y-tiles
    } else {
        do_scan_x(in, out, bid - q - 1u);            // 8192 x-blocks
    }
}

extern "C" void kernel_launch(void* const* d_in, const int* in_sizes, int n_in,
                              void* d_out, int out_size) {
    const float* in = (const float*)d_in[0];
    float* out = (float*)d_out;
    fused_scan_kernel<<<GRID_BLOCKS, 256>>>(in, out);
}

// round 13
// speedup vs baseline: 1.1535x; 1.1535x over previous
#include <cuda_runtime.h>
#include <cstdint>

// Problem: input [B=128, C=2, H=512, W=512] fp32.
// out[:,0] = inclusive cumsum along x (contiguous axis)
// out[:,1] = inclusive cumsum along y (stride-W axis)
//
// Two CONCURRENT kernels via fork/join events on static side streams:
//  scan_x_kernel: warp-per-row float4 scan, 0 smem, full occupancy.
//  scan_y_kernel: 512x16 tile staged through 34KB smem (R10's exact path:
//    no skew, no streaming hints — both measured as regressions).
// Splitting removes the 34KB smem tax the fused kernel charged every x-block,
// while event fork/join keeps both kernels co-resident on the SMs.

#define Bn 128
#define Wn 512
#define TCOLS 16                    // tile width (columns)
#define TSEG 32                     // rows per scan segment
#define NSEG 16                     // 512 / 32
#define Y_BLOCKS 4096               // 128 images * (512/16) col-tiles
#define X_BLOCKS 8192               // 65536 rows / 8 warps

// ---------------------------------------------------------------------------
// x-kernel: one warp per row of channel 0.
// ---------------------------------------------------------------------------
__global__ void __launch_bounds__(256) scan_x_kernel(const float* __restrict__ in,
                                                     float* __restrict__ out) {
    const unsigned gwarp = blockIdx.x * 8u + (threadIdx.x >> 5);   // 0..65535
    const unsigned lane  = threadIdx.x & 31u;

    const unsigned b = gwarp >> 9;
    const unsigned y = gwarp & 511u;

    const size_t base = ((size_t)(b * 2u + 0u) * Wn + y) * Wn;  // channel 0
    const float4* __restrict__ in4  = (const float4*)(in + base);
    float4* __restrict__       out4 = (float4*)(out + base);

    float carry = 0.0f;
#pragma unroll
    for (int it = 0; it < 4; ++it) {
        float4 v = in4[it * 32 + lane];

        float s0 = v.x;
        float s1 = s0 + v.y;
        float s2 = s1 + v.z;
        float s3 = s2 + v.w;

        float incl = s3;
#pragma unroll
        for (int off = 1; off < 32; off <<= 1) {
            float n = __shfl_up_sync(0xffffffffu, incl, off);
            if (lane >= (unsigned)off) incl += n;
        }
        float excl = incl - s3 + carry;

        float4 o;
        o.x = s0 + excl;
        o.y = s1 + excl;
        o.z = s2 + excl;
        o.w = s3 + excl;
        out4[it * 32 + lane] = o;

        carry += __shfl_sync(0xffffffffu, incl, 31);
    }
}

// ---------------------------------------------------------------------------
// y-kernel: 512x16 tile of channel 1 through smem (exact R10 path).
// ---------------------------------------------------------------------------
__global__ void __launch_bounds__(256) scan_y_kernel(const float* __restrict__ in,
                                                     float* __restrict__ out) {
    __shared__ float tile[TCOLS * Wn];       // 32 KB
    __shared__ float spine[NSEG * TCOLS];    // 1 KB
    __shared__ float pre[NSEG * TCOLS];      // 1 KB

    const unsigned tid = threadIdx.x;
    const unsigned ybid = blockIdx.x;
    const unsigned b   = ybid >> 5;          // image (32 col-tiles per image)
    const unsigned tc  = ybid & 31u;         // col-tile
    const unsigned col0 = tc * TCOLS;

    const size_t base = ((size_t)(b * 2u + 1u) * Wn) * Wn + col0;  // ch1 row0

    const unsigned quad = tid & 3u;          // float4 within 16-col tile row
    const unsigned r0   = tid >> 2;          // 0..63
    float4* __restrict__ tile4 = (float4*)tile;

    // ---- load: 2048 float4s, 8 per thread, coalesced, independent ----
    {
        const float4* __restrict__ in4 = (const float4*)(in + base);
#pragma unroll
        for (int batch = 0; batch < 8; ++batch) {
            const unsigned row = batch * 64u + r0;
            tile4[row * 4u + quad] = in4[(size_t)row * 128u + quad];
        }
    }
    __syncthreads();

    // ---- scan: thread (c, s) scans rows [s*32, s*32+32) of column c ----
    const unsigned c = tid & 15u;
    const unsigned s = tid >> 4;
    {
        float acc = 0.0f;
#pragma unroll
        for (int i = 0; i < TSEG; ++i) {
            const unsigned idx = (s * TSEG + i) * TCOLS + c;
            acc += tile[idx];
            tile[idx] = acc;               // in-place inclusive prefix
        }
        spine[s * TCOLS + c] = acc;        // segment total
    }
    __syncthreads();

    // ---- spine prefix: pre[s][c] = sum of spine[s2][c], s2 < s ----
    {
        float off = 0.0f;
        for (unsigned s2 = 0; s2 < s; ++s2)
            off += spine[s2 * TCOLS + c];
        pre[s * TCOLS + c] = off;
    }
    __syncthreads();

    // ---- store: same float4 mapping as load (fully coalesced) ----
    {
        float4* __restrict__ out4 = (float4*)(out + base);
        const float* __restrict__ prow = pre + quad * 4u;   // 4 col offsets
#pragma unroll
        for (int batch = 0; batch < 8; ++batch) {
            const unsigned row = batch * 64u + r0;
            const unsigned seg = row >> 5;                  // row / TSEG
            float4 v = tile4[row * 4u + quad];
            v.x += prow[seg * TCOLS + 0];
            v.y += prow[seg * TCOLS + 1];
            v.z += prow[seg * TCOLS + 2];
            v.w += prow[seg * TCOLS + 3];
            out4[(size_t)row * 128u + quad] = v;
        }
    }
}

// ---------------------------------------------------------------------------
// Static side streams + events for the capture-legal fork/join. Created in a
// static initializer (host objects only, before the harness's memory
// baseline; no device allocation in kernel_launch).
// ---------------------------------------------------------------------------
static cudaStream_t g_sx, g_sy;
static cudaEvent_t g_fork, g_jx, g_jy;

namespace {
struct StreamInit {
    StreamInit() {
        cudaStreamCreateWithFlags(&g_sx, cudaStreamNonBlocking);
        cudaStreamCreateWithFlags(&g_sy, cudaStreamNonBlocking);
        cudaEventCreateWithFlags(&g_fork, cudaEventDisableTiming);
        cudaEventCreateWithFlags(&g_jx, cudaEventDisableTiming);
        cudaEventCreateWithFlags(&g_jy, cudaEventDisableTiming);
    }
};
StreamInit g_stream_init;
}  // namespace

extern "C" void kernel_launch(void* const* d_in, const int* in_sizes, int n_in,
                              void* d_out, int out_size) {
    const float* in = (const float*)d_in[0];
    float* out = (float*)d_out;

    // fork from the (captured) default stream
    cudaEventRecord(g_fork, 0);
    cudaStreamWaitEvent(g_sx, g_fork, 0);
    cudaStreamWaitEvent(g_sy, g_fork, 0);

    scan_x_kernel<<<X_BLOCKS, 256, 0, g_sx>>>(in, out);
    scan_y_kernel<<<Y_BLOCKS, 256, 0, g_sy>>>(in, out);

    // join back into the default stream
    cudaEventRecord(g_jx, g_sx);
    cudaEventRecord(g_jy, g_sy);
    cudaStreamWaitEvent(0, g_jx, 0);
    cudaStreamWaitEvent(0, g_jy, 0);
}

// round 14
// speedup vs baseline: 1.3457x; 1.1667x over previous
#include <cuda_runtime.h>
#include <cstdint>

// Problem: input [B=128, C=2, H=512, W=512] fp32.
// out[:,0] = inclusive cumsum along x (contiguous axis)
// out[:,1] = inclusive cumsum along y (stride-W axis)
//
// One fused kernel, 512 threads/block, everything register-resident:
//  x-role (4096 blocks): one warp per row (16 rows/block), float4 warp-scan.
//  y-role (2048 blocks): 512x32 column tile, NO smem data staging.
//    Thread (quad 0..7, r 0..63) loads 8 consecutive rows as float4
//    (4 cols), scans locally in registers, chunk totals combined by
//    stride-8/16 shfl_up within the warp, warp totals through a 2KB smem
//    spine (single __syncthreads), then adds offsets and stores.
//    Per-block smem traffic: ~4KB (was ~384KB effective in the tile design
//    that ncu showed to be L1-bound at 78.5%).
// Interleaved bid%3==0 -> y so both traffic types share every wave.

#define Wn 512
#define YCOLS 32                    // columns per y-block
#define Y_BLOCKS 2048               // 128 images * (512/32) col-tiles
#define X_BLOCKS 4096               // 65536 rows / 16 warps
#define GRID_BLOCKS (Y_BLOCKS + X_BLOCKS)
#define NTHREADS 512

__device__ __forceinline__ float4 shfl_up4(float4 v, int delta) {
    float4 r;
    r.x = __shfl_up_sync(0xffffffffu, v.x, delta);
    r.y = __shfl_up_sync(0xffffffffu, v.y, delta);
    r.z = __shfl_up_sync(0xffffffffu, v.z, delta);
    r.w = __shfl_up_sync(0xffffffffu, v.w, delta);
    return r;
}

__device__ __forceinline__ float4 shfl_idx4(float4 v, int src) {
    float4 r;
    r.x = __shfl_sync(0xffffffffu, v.x, src);
    r.y = __shfl_sync(0xffffffffu, v.y, src);
    r.z = __shfl_sync(0xffffffffu, v.z, src);
    r.w = __shfl_sync(0xffffffffu, v.w, src);
    return r;
}

// ---------------------------------------------------------------------------
// x-role: one warp per row of channel 0 (16 warps per block).
// ---------------------------------------------------------------------------
__device__ __forceinline__ void do_scan_x(const float* __restrict__ in,
                                          float* __restrict__ out,
                                          unsigned xbid) {
    const unsigned gwarp = xbid * 16u + (threadIdx.x >> 5);  // 0..65535
    const unsigned lane  = threadIdx.x & 31u;

    const unsigned b = gwarp >> 9;
    const unsigned y = gwarp & 511u;

    const size_t base = ((size_t)(b * 2u + 0u) * Wn + y) * Wn;  // channel 0
    const float4* __restrict__ in4  = (const float4*)(in + base);
    float4* __restrict__       out4 = (float4*)(out + base);

    float carry = 0.0f;
#pragma unroll
    for (int it = 0; it < 4; ++it) {
        float4 v = in4[it * 32 + lane];

        float s0 = v.x;
        float s1 = s0 + v.y;
        float s2 = s1 + v.z;
        float s3 = s2 + v.w;

        float incl = s3;
#pragma unroll
        for (int off = 1; off < 32; off <<= 1) {
            float n = __shfl_up_sync(0xffffffffu, incl, off);
            if (lane >= (unsigned)off) incl += n;
        }
        float excl = incl - s3 + carry;

        float4 o;
        o.x = s0 + excl;
        o.y = s1 + excl;
        o.z = s2 + excl;
        o.w = s3 + excl;
        out4[it * 32 + lane] = o;

        carry += __shfl_sync(0xffffffffu, incl, 31);
    }
}

// ---------------------------------------------------------------------------
// y-role: 512x32 column tile of channel 1, register-resident scan.
// ---------------------------------------------------------------------------
__device__ __forceinline__ void do_scan_y(const float* __restrict__ in,
                                          float* __restrict__ out,
                                          unsigned ybid,
                                          float4* __restrict__ wtot) {
    const unsigned tid  = threadIdx.x;
    const unsigned quad = tid & 7u;            // float4 column group (0..7)
    const unsigned r    = tid >> 3;            // row-chunk (0..63)
    const unsigned w    = tid >> 5;            // warp (0..15)
    const unsigned lane = tid & 31u;
    const unsigned rloc = lane >> 3;           // row-chunk within warp (0..3)

    const unsigned b  = ybid >> 4;             // image (16 col-tiles/image)
    const unsigned tc = ybid & 15u;            // col-tile
    const size_t base = ((size_t)(b * 2u + 1u) * Wn) * Wn + tc * YCOLS;

    const float4* __restrict__ in4 = (const float4*)(in + base);
    float4* __restrict__ out4      = (float4*)(out + base);

    // ---- load 8 consecutive rows (float4 each) + local inclusive scan ----
    // Warp instruction footprint: 4 rows x 128B dense lines, 8 in flight.
    float4 v[8];
    const unsigned row0 = r * 8u;
#pragma unroll
    for (int j = 0; j < 8; ++j)
        v[j] = in4[(size_t)(row0 + j) * (Wn / 4) + quad];
#pragma unroll
    for (int j = 1; j < 8; ++j) {
        v[j].x += v[j - 1].x;
        v[j].y += v[j - 1].y;
        v[j].z += v[j - 1].z;
        v[j].w += v[j - 1].w;
    }

    // ---- warp scan over the 4 row-chunks (stride 8 lanes per chunk) ----
    float4 incl = v[7];
    {
        float4 n = shfl_up4(incl, 8);
        if (rloc >= 1) { incl.x += n.x; incl.y += n.y; incl.z += n.z; incl.w += n.w; }
        n = shfl_up4(incl, 16);
        if (rloc >= 2) { incl.x += n.x; incl.y += n.y; incl.z += n.z; incl.w += n.w; }
    }
    // exclusive offset within warp for this thread's chunk
    float4 wexcl;
    wexcl.x = incl.x - v[7].x;
    wexcl.y = incl.y - v[7].y;
    wexcl.z = incl.z - v[7].z;
    wexcl.w = incl.w - v[7].w;

    // warp total for this quad = inclusive value at rloc==3 (lane quad+24)
    float4 wsum = shfl_idx4(incl, (int)(quad + 24u));

    // ---- spine: 16 warps x 8 quads of float4 through smem ----
    if (rloc == 3u)
        wtot[w * 8u + quad] = wsum;
    __syncthreads();

    float4 off = wexcl;
    for (unsigned w2 = 0; w2 < w; ++w2) {
        float4 t = wtot[w2 * 8u + quad];
        off.x += t.x; off.y += t.y; off.z += t.z; off.w += t.w;
    }

    // ---- add offsets and store (same dense pattern as load) ----
#pragma unroll
    for (int j = 0; j < 8; ++j) {
        float4 o;
        o.x = v[j].x + off.x;
        o.y = v[j].y + off.y;
        o.z = v[j].z + off.z;
        o.w = v[j].w + off.w;
        out4[(size_t)(row0 + j) * (Wn / 4) + quad] = o;
    }
}

__global__ void __launch_bounds__(NTHREADS) fused_scan_kernel(const float* __restrict__ in,
                                                              float* __restrict__ out) {
    __shared__ float4 wtot[16 * 8];          // 2 KB spine

    const unsigned bid = blockIdx.x;
    const unsigned q = bid / 3u;
    if (bid == q * 3u) {
        do_scan_y(in, out, q, wtot);             // 2048 y-blocks
    } else {
        do_scan_x(in, out, bid - q - 1u);        // 4096 x-blocks
    }
}

extern "C" void kernel_launch(void* const* d_in, const int* in_sizes, int n_in,
                              void* d_out, int out_size) {
    const float* in = (const float*)d_in[0];
    float* out = (float*)d_out;
    fused_scan_kernel<<<GRID_BLOCKS, NTHREADS>>>(in, out);
}